// round 7
// baseline (speedup 1.0000x reference)
#include <cuda_runtime.h>
#include <cuda_bf16.h>
#include <math.h>

// ---------------------------------------------------------------------------
// Problem constants
// ---------------------------------------------------------------------------
#define BATCH     2048
#define SDIM      64
#define ADIM      16
#define HID       256
#define TDIM      32
#define TSTEPS    100
#define CAT       112            // ADIM + TDIM + SDIM
#define RPC       16             // rows per CTA
#define NRP       8              // row-pairs per CTA
#define NCTA      (BATCH / RPC)  // 128
#define NTHR      256            // 128 col-pair threads x 2 k-halves

typedef unsigned long long ull;

// ---------------------------------------------------------------------------
// Precomputed tables
// ---------------------------------------------------------------------------
__device__ float g_temb[TSTEPS * TDIM];
__device__ float g_srac[TSTEPS];
__device__ float g_sracm1[TSTEPS];
__device__ float g_c1[TSTEPS];
__device__ float g_c2[TSTEPS];
__device__ float g_sigma[TSTEPS];

// ---------------------------------------------------------------------------
// f32x2 helpers
// ---------------------------------------------------------------------------
__device__ __forceinline__ ull pack2(float lo, float hi) {
    ull r; asm("mov.b64 %0, {%1, %2};" : "=l"(r) : "f"(lo), "f"(hi)); return r;
}
__device__ __forceinline__ void unpack2(ull v, float& lo, float& hi) {
    asm("mov.b64 {%0, %1}, %2;" : "=f"(lo), "=f"(hi) : "l"(v));
}
__device__ __forceinline__ void fma2(ull& d, ull a, ull b) {
    asm("fma.rn.f32x2 %0, %1, %2, %0;" : "+l"(d) : "l"(a), "l"(b));
}
__device__ __forceinline__ ull add2(ull a, ull b) {
    ull r; asm("add.rn.f32x2 %0, %1, %2;" : "=l"(r) : "l"(a), "l"(b)); return r;
}

__device__ __forceinline__ float mishf(float x) {
    float sp = fmaxf(x, 0.0f) + log1pf(expf(-fabsf(x)));
    return x * tanhf(sp);
}

// ---------------------------------------------------------------------------
// Prolog: VP schedule in f64 + per-timestep time-MLP (batch-invariant).
// ---------------------------------------------------------------------------
__global__ void __launch_bounds__(256) prolog_kernel(
    const float* __restrict__ tW1, const float* __restrict__ tb1,
    const float* __restrict__ tW2, const float* __restrict__ tb2)
{
    const int tid = threadIdx.x;
    const int i   = blockIdx.x;

    if (i == 0 && tid == 0) {
        const double T = (double)TSTEPS, bmax = 10.0, bmin = 0.1;
        double ac = 1.0;
        for (int idx = 0; idx < TSTEPS; ++idx) {
            double t      = (double)(idx + 1);
            double alpha  = exp(-bmin / T - 0.5 * (bmax - bmin) * (2.0 * t - 1.0) / (T * T));
            double beta   = 1.0 - alpha;
            double acp    = ac;
            ac            = ac * alpha;
            g_srac[idx]   = (float)sqrt(1.0 / ac);
            g_sracm1[idx] = (float)sqrt(1.0 / ac - 1.0);
            g_c1[idx]     = (float)(beta * sqrt(acp) / (1.0 - ac));
            g_c2[idx]     = (float)((1.0 - acp) * sqrt(alpha) / (1.0 - ac));
            double pv     = beta * (1.0 - acp) / (1.0 - ac);
            if (pv < 1e-20) pv = 1e-20;
            g_sigma[idx]  = (float)exp(0.5 * log(pv));
        }
    }

    __shared__ float emb[TDIM];
    __shared__ float hid[HID];

    if (tid < TDIM) {
        int   j    = tid & 15;
        float freq = expf((float)j * (-logf(10000.0f) / 15.0f));
        float ang  = (float)i * freq;
        emb[tid]   = (tid < 16) ? sinf(ang) : cosf(ang);
    }
    __syncthreads();
    {
        float a = tb1[tid];
#pragma unroll
        for (int j = 0; j < TDIM; ++j)
            a = fmaf(emb[j], tW1[j * HID + tid], a);
        hid[tid] = mishf(a);
    }
    __syncthreads();
    if (tid < TDIM) {
        float a = tb2[tid];
#pragma unroll 8
        for (int h = 0; h < HID; ++h)
            a = fmaf(hid[h], tW2[h * TDIM + tid], a);
        g_temb[i * TDIM + tid] = a;
    }
}

// ---------------------------------------------------------------------------
// Dense layer 256-out, thread tile = 8 row-pairs x 2 cols, k-split 2.
//   in  : smem ull[K][NRP] row-pair packed activations (broadcast LDS.128)
//   W   : gmem fp32 [K][256]; 2 cols via LDG.64 (coalesced 256B/warp)
//   out : smem ull[256][NRP] — MAY alias `in` (sync before first write)
//   red : smem ull[256][NRP] — ks=1 partial
// ks=0 folds bias into acc init; mish pass combines hbuf+red in a spread pass.
// 3 __syncthreads per layer, no serialized reduction stages.
// ---------------------------------------------------------------------------
template <int K, bool INPLACE>
__device__ __forceinline__ void dense2ks(
    const ull* __restrict__ in,
    const float* __restrict__ W,
    const float* __restrict__ b,
    ull* __restrict__ out,
    ull* __restrict__ red,
    int cg, int ks, int tid)
{
    const int c0 = cg * 2;
    ull acc[NRP][2];
    if (ks == 0) {
        const ull b0 = pack2(b[c0], b[c0]);
        const ull b1 = pack2(b[c0 + 1], b[c0 + 1]);
#pragma unroll
        for (int rp = 0; rp < NRP; ++rp) { acc[rp][0] = b0; acc[rp][1] = b1; }
    } else {
#pragma unroll
        for (int rp = 0; rp < NRP; ++rp) { acc[rp][0] = 0; acc[rp][1] = 0; }
    }

    const int kn = K / 2;
    const int kb = ks * kn;

#pragma unroll 4
    for (int kk = 0; kk < kn; ++kk) {
        const int k = kb + kk;
        const ulonglong2 a01 = *(const ulonglong2*)(in + k * NRP + 0);
        const ulonglong2 a23 = *(const ulonglong2*)(in + k * NRP + 2);
        const ulonglong2 a45 = *(const ulonglong2*)(in + k * NRP + 4);
        const ulonglong2 a67 = *(const ulonglong2*)(in + k * NRP + 6);
        const float2 wf = *(const float2*)(W + k * HID + c0);
        const ull w0 = pack2(wf.x, wf.x);
        const ull w1 = pack2(wf.y, wf.y);
        fma2(acc[0][0], a01.x, w0);  fma2(acc[0][1], a01.x, w1);
        fma2(acc[1][0], a01.y, w0);  fma2(acc[1][1], a01.y, w1);
        fma2(acc[2][0], a23.x, w0);  fma2(acc[2][1], a23.x, w1);
        fma2(acc[3][0], a23.y, w0);  fma2(acc[3][1], a23.y, w1);
        fma2(acc[4][0], a45.x, w0);  fma2(acc[4][1], a45.x, w1);
        fma2(acc[5][0], a45.y, w0);  fma2(acc[5][1], a45.y, w1);
        fma2(acc[6][0], a67.x, w0);  fma2(acc[6][1], a67.x, w1);
        fma2(acc[7][0], a67.y, w0);  fma2(acc[7][1], a67.y, w1);
    }

    if (INPLACE) __syncthreads();          // all reads of `in` complete

    ull* o = (ks == 0 ? out : red) + c0 * NRP;
#pragma unroll
    for (int cc = 0; cc < 2; ++cc)
#pragma unroll
        for (int rp = 0; rp < NRP; ++rp)
            o[cc * NRP + rp] = acc[rp][cc];
    __syncthreads();

    // combine + mish spread pass: 2048 ull / 256 threads = 8 each
    {
        ull* ph = out + tid * 8;
        const ull* pr = red + tid * 8;
#pragma unroll
        for (int j = 0; j < 8; ++j) {
            ull v = add2(ph[j], pr[j]);
            float lo, hi; unpack2(v, lo, hi);
            ph[j] = pack2(mishf(lo), mishf(hi));
        }
    }
    __syncthreads();
}

// ---------------------------------------------------------------------------
// Fused sampler: CTA owns 16 rows for all 100 steps.
// ---------------------------------------------------------------------------
__global__ void __launch_bounds__(NTHR, 1) sampler_kernel(
    const float* __restrict__ state,
    const float* __restrict__ x_init,
    const float* __restrict__ noise,
    const float* __restrict__ W1, const float* __restrict__ b1,
    const float* __restrict__ W2, const float* __restrict__ b2,
    const float* __restrict__ W3, const float* __restrict__ b3,
    const float* __restrict__ W4, const float* __restrict__ b4,
    float* __restrict__ out)
{
    __shared__ __align__(16) ull a0[CAT * NRP];        //  7.0 KB  layer-1 input
    __shared__ __align__(16) ull hbuf[HID * NRP];      // 16.0 KB  layers 1-3 (in-place)
    __shared__ __align__(16) ull red[HID * NRP];       // 16.0 KB  ks=1 partials
    __shared__ __align__(16) ull red4[NRP * ADIM * 2]; //  2.0 KB  L4 partials

    const int tid  = threadIdx.x;
    const int cg   = tid & 127;      // col-pair 0..127
    const int ks   = tid >> 7;       // k-half 0..1
    const int row0 = blockIdx.x * RPC;

    // ---- one-time fills (row-pair packed) ----
    if (tid < 128) {                 // x: 16 feats x 8 rp
        int f = tid >> 3, rp = tid & 7;
        a0[f * NRP + rp] = pack2(x_init[(row0 + 2 * rp)     * ADIM + f],
                                 x_init[(row0 + 2 * rp + 1) * ADIM + f]);
    }
#pragma unroll
    for (int p = 0; p < 2; ++p) {    // state: 64 feats x 8 rp = 512
        int idx = tid + p * 256;
        int f = idx >> 3, rp = idx & 7;
        a0[(ADIM + TDIM + f) * NRP + rp] =
            pack2(state[(row0 + 2 * rp)     * SDIM + f],
                  state[(row0 + 2 * rp + 1) * SDIM + f]);
    }

    for (int s = 0; s < TSTEPS; ++s) {
        const int i = TSTEPS - 1 - s;

        {   // temb: 32 feats x 8 rp = 256 (row-invariant)
            int f = tid >> 3, rp = tid & 7;
            float t = g_temb[i * TDIM + f];
            a0[(ADIM + f) * NRP + rp] = pack2(t, t);
        }
        __syncthreads();

        dense2ks<CAT, false>(a0,   W1, b1, hbuf, red, cg, ks, tid);
        dense2ks<HID, true >(hbuf, W2, b2, hbuf, red, cg, ks, tid);
        dense2ks<HID, true >(hbuf, W3, b3, hbuf, red, cg, ks, tid);

        // ---- layer 4 (256 -> 16): thread = (k-half, rp, c) ----
        {
            const int c  = tid & 15;
            const int rp = (tid >> 4) & 7;
            const int k4 = tid >> 7;        // 0..1
            ull acc = 0;
            const int kb = k4 * 128;
#pragma unroll 4
            for (int kk = 0; kk < 128; ++kk) {
                const int k = kb + kk;
                const float w = W4[k * ADIM + c];
                fma2(acc, hbuf[k * NRP + rp], pack2(w, w));
            }
            red4[(rp * ADIM + c) * 2 + k4] = acc;
        }
        __syncthreads();

        // ---- reduce + posterior (128 threads: rp, c) ----
        if (tid < 128) {
            const int rp = tid >> 4, c = tid & 15;
            const ull* r = red4 + (rp * ADIM + c) * 2;
            ull e = add2(r[0], r[1]);
            float e0, e1; unpack2(e, e0, e1);
            const float bb = b4[c];
            e0 += bb; e1 += bb;

            float x0, x1; unpack2(a0[c * NRP + rp], x0, x1);
            const float sr = g_srac[i], srm = g_sracm1[i];
            const float c1 = g_c1[i],   c2  = g_c2[i];

            float r0 = fminf(fmaxf(sr * x0 - srm * e0, -1.0f), 1.0f);
            float r1 = fminf(fmaxf(sr * x1 - srm * e1, -1.0f), 1.0f);
            float m0 = c1 * r0 + c2 * x0;
            float m1 = c1 * r1 + c2 * x1;

            if (i > 0) {
                const float sg = g_sigma[i];
                const float* nz = noise + (size_t)s * BATCH * ADIM;
                float n0 = nz[(row0 + 2 * rp)     * ADIM + c];
                float n1 = nz[(row0 + 2 * rp + 1) * ADIM + c];
                a0[c * NRP + rp] = pack2(fmaf(sg, n0, m0), fmaf(sg, n1, m1));
            } else {
                out[(row0 + 2 * rp)     * ADIM + c] = fminf(fmaxf(m0, -1.0f), 1.0f);
                out[(row0 + 2 * rp + 1) * ADIM + c] = fminf(fmaxf(m1, -1.0f), 1.0f);
            }
        }
        __syncthreads();
    }
}

// ---------------------------------------------------------------------------
// kernel_launch
// ---------------------------------------------------------------------------
extern "C" void kernel_launch(void* const* d_in, const int* in_sizes, int n_in,
                              void* d_out, int out_size)
{
    const float* state  = (const float*)d_in[0];
    const float* x_init = (const float*)d_in[1];
    const float* noise  = (const float*)d_in[2];
    const float* tW1    = (const float*)d_in[3];
    const float* tb1    = (const float*)d_in[4];
    const float* tW2    = (const float*)d_in[5];
    const float* tb2    = (const float*)d_in[6];
    const float* W1     = (const float*)d_in[7];
    const float* b1     = (const float*)d_in[8];
    const float* W2     = (const float*)d_in[9];
    const float* b2     = (const float*)d_in[10];
    const float* W3     = (const float*)d_in[11];
    const float* b3     = (const float*)d_in[12];
    const float* W4     = (const float*)d_in[13];
    const float* b4     = (const float*)d_in[14];
    float* out          = (float*)d_out;

    prolog_kernel<<<TSTEPS, 256>>>(tW1, tb1, tW2, tb2);
    sampler_kernel<<<NCTA, NTHR>>>(state, x_init, noise,
                                   W1, b1, W2, b2, W3, b3, W4, b4, out);
}

// round 8
// speedup vs baseline: 1.1544x; 1.1544x over previous
#include <cuda_runtime.h>
#include <cuda_bf16.h>
#include <math.h>

// ---------------------------------------------------------------------------
// Problem constants
// ---------------------------------------------------------------------------
#define BATCH     2048
#define SDIM      64
#define ADIM      16
#define HID       256
#define TDIM      32
#define TSTEPS    100
#define CAT       112            // ADIM + TDIM + SDIM
#define RPC       16             // rows per CTA
#define NRP       8              // row-pairs per CTA
#define NCTA      (BATCH / RPC)  // 128
#define NTHR      512            // 128 col-pair threads x 4 k-quarters

typedef unsigned long long ull;

// ---------------------------------------------------------------------------
// Precomputed tables
// ---------------------------------------------------------------------------
__device__ float g_temb[TSTEPS * TDIM];
__device__ float g_srac[TSTEPS];
__device__ float g_sracm1[TSTEPS];
__device__ float g_c1[TSTEPS];
__device__ float g_c2[TSTEPS];
__device__ float g_sigma[TSTEPS];

// ---------------------------------------------------------------------------
// f32x2 helpers
// ---------------------------------------------------------------------------
__device__ __forceinline__ ull pack2(float lo, float hi) {
    ull r; asm("mov.b64 %0, {%1, %2};" : "=l"(r) : "f"(lo), "f"(hi)); return r;
}
__device__ __forceinline__ void unpack2(ull v, float& lo, float& hi) {
    asm("mov.b64 {%0, %1}, %2;" : "=f"(lo), "=f"(hi) : "l"(v));
}
__device__ __forceinline__ void fma2(ull& d, ull a, ull b) {
    asm("fma.rn.f32x2 %0, %1, %2, %0;" : "+l"(d) : "l"(a), "l"(b));
}
__device__ __forceinline__ ull add2(ull a, ull b) {
    ull r; asm("add.rn.f32x2 %0, %1, %2;" : "=l"(r) : "l"(a), "l"(b)); return r;
}

__device__ __forceinline__ float mishf(float x) {
    float sp = fmaxf(x, 0.0f) + log1pf(expf(-fabsf(x)));
    return x * tanhf(sp);
}

// ---------------------------------------------------------------------------
// Prolog: VP schedule in f64 + per-timestep time-MLP (batch-invariant).
// ---------------------------------------------------------------------------
__global__ void __launch_bounds__(256) prolog_kernel(
    const float* __restrict__ tW1, const float* __restrict__ tb1,
    const float* __restrict__ tW2, const float* __restrict__ tb2)
{
    const int tid = threadIdx.x;
    const int i   = blockIdx.x;

    if (i == 0 && tid == 0) {
        const double T = (double)TSTEPS, bmax = 10.0, bmin = 0.1;
        double ac = 1.0;
        for (int idx = 0; idx < TSTEPS; ++idx) {
            double t      = (double)(idx + 1);
            double alpha  = exp(-bmin / T - 0.5 * (bmax - bmin) * (2.0 * t - 1.0) / (T * T));
            double beta   = 1.0 - alpha;
            double acp    = ac;
            ac            = ac * alpha;
            g_srac[idx]   = (float)sqrt(1.0 / ac);
            g_sracm1[idx] = (float)sqrt(1.0 / ac - 1.0);
            g_c1[idx]     = (float)(beta * sqrt(acp) / (1.0 - ac));
            g_c2[idx]     = (float)((1.0 - acp) * sqrt(alpha) / (1.0 - ac));
            double pv     = beta * (1.0 - acp) / (1.0 - ac);
            if (pv < 1e-20) pv = 1e-20;
            g_sigma[idx]  = (float)exp(0.5 * log(pv));
        }
    }

    __shared__ float emb[TDIM];
    __shared__ float hid[HID];

    if (tid < TDIM) {
        int   j    = tid & 15;
        float freq = expf((float)j * (-logf(10000.0f) / 15.0f));
        float ang  = (float)i * freq;
        emb[tid]   = (tid < 16) ? sinf(ang) : cosf(ang);
    }
    __syncthreads();
    {
        float a = tb1[tid];
#pragma unroll
        for (int j = 0; j < TDIM; ++j)
            a = fmaf(emb[j], tW1[j * HID + tid], a);
        hid[tid] = mishf(a);
    }
    __syncthreads();
    if (tid < TDIM) {
        float a = tb2[tid];
#pragma unroll 8
        for (int h = 0; h < HID; ++h)
            a = fmaf(hid[h], tW2[h * TDIM + tid], a);
        g_temb[i * TDIM + tid] = a;
    }
}

// ---------------------------------------------------------------------------
// Dense layer 256-out, thread tile = 8 row-pairs x 2 cols, k-split 4.
//   in  : smem ull[K][NRP] row-pair packed activations (broadcast LDS.128)
//   W   : gmem fp32 [K][256]; 2 cols via LDG.64 (coalesced 256B/warp)
//   out : smem ull[256][NRP] — MAY alias `in`
//   red : smem ull[256][NRP]
// Staged parallel reduction: {ks0->out(+bias), ks1->red} then {ks2+=out,
// ks3+=red}, then mish spread pass combines out+red. 512 threads/CTA so
// 16 warps/SM hide LDS/LDG latency (R7's binder was 8-warp issue starvation).
// ---------------------------------------------------------------------------
template <int K, bool INPLACE>
__device__ __forceinline__ void dense4ks(
    const ull* __restrict__ in,
    const float* __restrict__ W,
    const float* __restrict__ b,
    ull* __restrict__ out,
    ull* __restrict__ red,
    int cg, int ks, int tid)
{
    const int c0 = cg * 2;
    ull acc[NRP][2];
    if (ks == 0) {
        const ull b0 = pack2(b[c0], b[c0]);
        const ull b1 = pack2(b[c0 + 1], b[c0 + 1]);
#pragma unroll
        for (int rp = 0; rp < NRP; ++rp) { acc[rp][0] = b0; acc[rp][1] = b1; }
    } else {
#pragma unroll
        for (int rp = 0; rp < NRP; ++rp) { acc[rp][0] = 0; acc[rp][1] = 0; }
    }

    const int kn = K / 4;
    const int kb = ks * kn;

#pragma unroll 4
    for (int kk = 0; kk < kn; ++kk) {
        const int k = kb + kk;
        const ulonglong2 a01 = *(const ulonglong2*)(in + k * NRP + 0);
        const ulonglong2 a23 = *(const ulonglong2*)(in + k * NRP + 2);
        const ulonglong2 a45 = *(const ulonglong2*)(in + k * NRP + 4);
        const ulonglong2 a67 = *(const ulonglong2*)(in + k * NRP + 6);
        const float2 wf = *(const float2*)(W + k * HID + c0);
        const ull w0 = pack2(wf.x, wf.x);
        const ull w1 = pack2(wf.y, wf.y);
        fma2(acc[0][0], a01.x, w0);  fma2(acc[0][1], a01.x, w1);
        fma2(acc[1][0], a01.y, w0);  fma2(acc[1][1], a01.y, w1);
        fma2(acc[2][0], a23.x, w0);  fma2(acc[2][1], a23.x, w1);
        fma2(acc[3][0], a23.y, w0);  fma2(acc[3][1], a23.y, w1);
        fma2(acc[4][0], a45.x, w0);  fma2(acc[4][1], a45.x, w1);
        fma2(acc[5][0], a45.y, w0);  fma2(acc[5][1], a45.y, w1);
        fma2(acc[6][0], a67.x, w0);  fma2(acc[6][1], a67.x, w1);
        fma2(acc[7][0], a67.y, w0);  fma2(acc[7][1], a67.y, w1);
    }

    if (INPLACE) __syncthreads();          // all reads of `in` complete

    // stage 1: ks0 -> out, ks1 -> red (disjoint, parallel)
    if (ks < 2) {
        ull* o = (ks == 0 ? out : red) + c0 * NRP;
#pragma unroll
        for (int cc = 0; cc < 2; ++cc)
#pragma unroll
            for (int rp = 0; rp < NRP; ++rp)
                o[cc * NRP + rp] = acc[rp][cc];
    }
    __syncthreads();

    // stage 2: ks2 += out, ks3 += red (disjoint, parallel)
    if (ks >= 2) {
        ull* o = (ks == 2 ? out : red) + c0 * NRP;
#pragma unroll
        for (int cc = 0; cc < 2; ++cc)
#pragma unroll
            for (int rp = 0; rp < NRP; ++rp)
                o[cc * NRP + rp] = add2(o[cc * NRP + rp], acc[rp][cc]);
    }
    __syncthreads();

    // combine + mish spread pass: 2048 ull / 512 threads = 4 each
    {
        ull* ph = out + tid * 4;
        const ull* pr = red + tid * 4;
#pragma unroll
        for (int j = 0; j < 4; ++j) {
            ull v = add2(ph[j], pr[j]);
            float lo, hi; unpack2(v, lo, hi);
            ph[j] = pack2(mishf(lo), mishf(hi));
        }
    }
    __syncthreads();
}

// ---------------------------------------------------------------------------
// Fused sampler: CTA owns 16 rows for all 100 steps. 512 threads.
// ---------------------------------------------------------------------------
__global__ void __launch_bounds__(NTHR, 1) sampler_kernel(
    const float* __restrict__ state,
    const float* __restrict__ x_init,
    const float* __restrict__ noise,
    const float* __restrict__ W1, const float* __restrict__ b1,
    const float* __restrict__ W2, const float* __restrict__ b2,
    const float* __restrict__ W3, const float* __restrict__ b3,
    const float* __restrict__ W4, const float* __restrict__ b4,
    float* __restrict__ out)
{
    __shared__ __align__(16) ull a0[CAT * NRP];        //  7.0 KB  layer-1 input
    __shared__ __align__(16) ull hbuf[HID * NRP];      // 16.0 KB  layers 1-3 (in-place)
    __shared__ __align__(16) ull red[HID * NRP];       // 16.0 KB  partials
    __shared__ __align__(16) ull red4[NRP * ADIM * 4]; //  4.0 KB  L4 partials

    const int tid  = threadIdx.x;
    const int cg   = tid & 127;      // col-pair 0..127
    const int ks   = tid >> 7;       // k-quarter 0..3
    const int row0 = blockIdx.x * RPC;

    // ---- one-time fills (row-pair packed) ----
    if (tid < 128) {                 // x: 16 feats x 8 rp
        int f = tid >> 3, rp = tid & 7;
        a0[f * NRP + rp] = pack2(x_init[(row0 + 2 * rp)     * ADIM + f],
                                 x_init[(row0 + 2 * rp + 1) * ADIM + f]);
    }
    {                                // state: 64 feats x 8 rp = 512
        int f = tid >> 3, rp = tid & 7;
        a0[(ADIM + TDIM + f) * NRP + rp] =
            pack2(state[(row0 + 2 * rp)     * SDIM + f],
                  state[(row0 + 2 * rp + 1) * SDIM + f]);
    }

    for (int s = 0; s < TSTEPS; ++s) {
        const int i = TSTEPS - 1 - s;

        if (tid < 256) {             // temb: 32 feats x 8 rp (row-invariant)
            int f = tid >> 3, rp = tid & 7;
            float t = g_temb[i * TDIM + f];
            a0[(ADIM + f) * NRP + rp] = pack2(t, t);
        }
        __syncthreads();

        dense4ks<CAT, false>(a0,   W1, b1, hbuf, red, cg, ks, tid);
        dense4ks<HID, true >(hbuf, W2, b2, hbuf, red, cg, ks, tid);
        dense4ks<HID, true >(hbuf, W3, b3, hbuf, red, cg, ks, tid);

        // ---- layer 4 (256 -> 16): thread = (k-quarter, rp, c) ----
        {
            const int c  = tid & 15;
            const int rp = (tid >> 4) & 7;
            const int k4 = tid >> 7;        // 0..3
            ull acc = 0;
            const int kb = k4 * 64;
#pragma unroll 4
            for (int kk = 0; kk < 64; ++kk) {
                const int k = kb + kk;
                const float w = W4[k * ADIM + c];
                fma2(acc, hbuf[k * NRP + rp], pack2(w, w));
            }
            red4[(rp * ADIM + c) * 4 + k4] = acc;
        }
        __syncthreads();

        // ---- reduce + posterior (128 threads: rp, c) ----
        if (tid < 128) {
            const int rp = tid >> 4, c = tid & 15;
            const ull* r = red4 + (rp * ADIM + c) * 4;
            ull e = add2(add2(r[0], r[1]), add2(r[2], r[3]));
            float e0, e1; unpack2(e, e0, e1);
            const float bb = b4[c];
            e0 += bb; e1 += bb;

            float x0, x1; unpack2(a0[c * NRP + rp], x0, x1);
            const float sr = g_srac[i], srm = g_sracm1[i];
            const float c1 = g_c1[i],   c2  = g_c2[i];

            float r0 = fminf(fmaxf(sr * x0 - srm * e0, -1.0f), 1.0f);
            float r1 = fminf(fmaxf(sr * x1 - srm * e1, -1.0f), 1.0f);
            float m0 = c1 * r0 + c2 * x0;
            float m1 = c1 * r1 + c2 * x1;

            if (i > 0) {
                const float sg = g_sigma[i];
                const float* nz = noise + (size_t)s * BATCH * ADIM;
                float n0 = nz[(row0 + 2 * rp)     * ADIM + c];
                float n1 = nz[(row0 + 2 * rp + 1) * ADIM + c];
                a0[c * NRP + rp] = pack2(fmaf(sg, n0, m0), fmaf(sg, n1, m1));
            } else {
                out[(row0 + 2 * rp)     * ADIM + c] = fminf(fmaxf(m0, -1.0f), 1.0f);
                out[(row0 + 2 * rp + 1) * ADIM + c] = fminf(fmaxf(m1, -1.0f), 1.0f);
            }
        }
        __syncthreads();
    }
}

// ---------------------------------------------------------------------------
// kernel_launch
// ---------------------------------------------------------------------------
extern "C" void kernel_launch(void* const* d_in, const int* in_sizes, int n_in,
                              void* d_out, int out_size)
{
    const float* state  = (const float*)d_in[0];
    const float* x_init = (const float*)d_in[1];
    const float* noise  = (const float*)d_in[2];
    const float* tW1    = (const float*)d_in[3];
    const float* tb1    = (const float*)d_in[4];
    const float* tW2    = (const float*)d_in[5];
    const float* tb2    = (const float*)d_in[6];
    const float* W1     = (const float*)d_in[7];
    const float* b1     = (const float*)d_in[8];
    const float* W2     = (const float*)d_in[9];
    const float* b2     = (const float*)d_in[10];
    const float* W3     = (const float*)d_in[11];
    const float* b3     = (const float*)d_in[12];
    const float* W4     = (const float*)d_in[13];
    const float* b4     = (const float*)d_in[14];
    float* out          = (float*)d_out;

    prolog_kernel<<<TSTEPS, 256>>>(tW1, tb1, tW2, tb2);
    sampler_kernel<<<NCTA, NTHR>>>(state, x_init, noise,
                                   W1, b1, W2, b2, W3, b3, W4, b4, out);
}

// round 9
// speedup vs baseline: 1.3231x; 1.1461x over previous
#include <cuda_runtime.h>
#include <cuda_bf16.h>
#include <math.h>

// ---------------------------------------------------------------------------
// Problem constants
// ---------------------------------------------------------------------------
#define BATCH     2048
#define SDIM      64
#define ADIM      16
#define HID       256
#define TDIM      32
#define TSTEPS    100
#define CAT       112            // ADIM + TDIM + SDIM
#define RPC       16             // rows per CTA
#define NRP       8              // row-pairs per CTA
#define NCTA      (BATCH / RPC)  // 128
#define NTHR      512            // 128 col-pair threads x 4 k-quarters

typedef unsigned long long ull;

// ---------------------------------------------------------------------------
// Precomputed tables
// ---------------------------------------------------------------------------
__device__ float g_temb[TSTEPS * TDIM];
__device__ float g_srac[TSTEPS];
__device__ float g_sracm1[TSTEPS];
__device__ float g_c1[TSTEPS];
__device__ float g_c2[TSTEPS];
__device__ float g_sigma[TSTEPS];

// ---------------------------------------------------------------------------
// f32x2 helpers
// ---------------------------------------------------------------------------
__device__ __forceinline__ ull pack2(float lo, float hi) {
    ull r; asm("mov.b64 %0, {%1, %2};" : "=l"(r) : "f"(lo), "f"(hi)); return r;
}
__device__ __forceinline__ void unpack2(ull v, float& lo, float& hi) {
    asm("mov.b64 {%0, %1}, %2;" : "=f"(lo), "=f"(hi) : "l"(v));
}
__device__ __forceinline__ void fma2(ull& d, ull a, ull b) {
    asm("fma.rn.f32x2 %0, %1, %2, %0;" : "+l"(d) : "l"(a), "l"(b));
}
__device__ __forceinline__ ull add2(ull a, ull b) {
    ull r; asm("add.rn.f32x2 %0, %1, %2;" : "=l"(r) : "l"(a), "l"(b)); return r;
}

// ---------------------------------------------------------------------------
// Fast exact-algebra mish:
//   mish(x) = x * tanh(softplus(x));  e^{softplus(x)} = 1 + e^x  (exact)
//   => tanh(sp) = ((1+u)^2 - 1)/((1+u)^2 + 1) = v/(v+2),  v = u^2 + 2u, u = e^x
// ex2.approx / rcp.approx errors ~2^-22 -> mish accurate to ~1e-6.
// Clamp x<=40 so u^2 stays finite (x>=40 => ratio==1 to fp32 precision).
// ---------------------------------------------------------------------------
__device__ __forceinline__ float mishf(float x) {
    const float LOG2E = 1.4426950408889634f;
    float xc = fminf(x, 40.0f);
    float u;
    asm("ex2.approx.f32 %0, %1;" : "=f"(u) : "f"(xc * LOG2E));
    float v = fmaf(u, u, u + u);          // u^2 + 2u
    float r;
    asm("rcp.approx.f32 %0, %1;" : "=f"(r) : "f"(v + 2.0f));
    return x * v * r;
}

// ---------------------------------------------------------------------------
// Prolog: VP schedule in f64 + per-timestep time-MLP (batch-invariant).
// ---------------------------------------------------------------------------
__global__ void __launch_bounds__(256) prolog_kernel(
    const float* __restrict__ tW1, const float* __restrict__ tb1,
    const float* __restrict__ tW2, const float* __restrict__ tb2)
{
    const int tid = threadIdx.x;
    const int i   = blockIdx.x;

    if (i == 0 && tid == 0) {
        const double T = (double)TSTEPS, bmax = 10.0, bmin = 0.1;
        double ac = 1.0;
        for (int idx = 0; idx < TSTEPS; ++idx) {
            double t      = (double)(idx + 1);
            double alpha  = exp(-bmin / T - 0.5 * (bmax - bmin) * (2.0 * t - 1.0) / (T * T));
            double beta   = 1.0 - alpha;
            double acp    = ac;
            ac            = ac * alpha;
            g_srac[idx]   = (float)sqrt(1.0 / ac);
            g_sracm1[idx] = (float)sqrt(1.0 / ac - 1.0);
            g_c1[idx]     = (float)(beta * sqrt(acp) / (1.0 - ac));
            g_c2[idx]     = (float)((1.0 - acp) * sqrt(alpha) / (1.0 - ac));
            double pv     = beta * (1.0 - acp) / (1.0 - ac);
            if (pv < 1e-20) pv = 1e-20;
            g_sigma[idx]  = (float)exp(0.5 * log(pv));
        }
    }

    __shared__ float emb[TDIM];
    __shared__ float hid[HID];

    if (tid < TDIM) {
        int   j    = tid & 15;
        float freq = expf((float)j * (-logf(10000.0f) / 15.0f));
        float ang  = (float)i * freq;
        emb[tid]   = (tid < 16) ? sinf(ang) : cosf(ang);
    }
    __syncthreads();
    {
        float a = tb1[tid];
#pragma unroll
        for (int j = 0; j < TDIM; ++j)
            a = fmaf(emb[j], tW1[j * HID + tid], a);
        hid[tid] = mishf(a);
    }
    __syncthreads();
    if (tid < TDIM) {
        float a = tb2[tid];
#pragma unroll 8
        for (int h = 0; h < HID; ++h)
            a = fmaf(hid[h], tW2[h * TDIM + tid], a);
        g_temb[i * TDIM + tid] = a;
    }
}

// ---------------------------------------------------------------------------
// Dense layer 256-out, thread tile = 8 row-pairs x 2 cols, k-split 4.
//   in  : smem ull[K][NRP] row-pair packed activations (broadcast LDS.128)
//   W   : gmem fp32 [K][256]; 2 cols via LDG.64 (coalesced 256B/warp)
//   out : smem ull[256][NRP] — MAY alias `in`
//   red : smem ull[256][NRP]
// Staged parallel reduction (all stores/loads vectorized to 128-bit):
// {ks0->out(+bias), ks1->red} then {ks2+=out, ks3+=red}, then a mish spread
// pass combines out+red. 16 warps/SM hide LDS/LDG latency.
// ---------------------------------------------------------------------------
template <int K, bool INPLACE>
__device__ __forceinline__ void dense4ks(
    const ull* __restrict__ in,
    const float* __restrict__ W,
    const float* __restrict__ b,
    ull* __restrict__ out,
    ull* __restrict__ red,
    int cg, int ks, int tid)
{
    const int c0 = cg * 2;
    ull acc[NRP][2];
    if (ks == 0) {
        const ull b0 = pack2(b[c0], b[c0]);
        const ull b1 = pack2(b[c0 + 1], b[c0 + 1]);
#pragma unroll
        for (int rp = 0; rp < NRP; ++rp) { acc[rp][0] = b0; acc[rp][1] = b1; }
    } else {
#pragma unroll
        for (int rp = 0; rp < NRP; ++rp) { acc[rp][0] = 0; acc[rp][1] = 0; }
    }

    const int kn = K / 4;
    const int kb = ks * kn;
    const ull*   ip = in + kb * NRP;
    const float* wp = W + kb * HID + c0;

#pragma unroll 8
    for (int kk = 0; kk < kn; ++kk) {
        const ulonglong2 a01 = *(const ulonglong2*)(ip + 0);
        const ulonglong2 a23 = *(const ulonglong2*)(ip + 2);
        const ulonglong2 a45 = *(const ulonglong2*)(ip + 4);
        const ulonglong2 a67 = *(const ulonglong2*)(ip + 6);
        const float2 wf = *(const float2*)wp;
        ip += NRP;
        wp += HID;
        const ull w0 = pack2(wf.x, wf.x);
        const ull w1 = pack2(wf.y, wf.y);
        fma2(acc[0][0], a01.x, w0);  fma2(acc[0][1], a01.x, w1);
        fma2(acc[1][0], a01.y, w0);  fma2(acc[1][1], a01.y, w1);
        fma2(acc[2][0], a23.x, w0);  fma2(acc[2][1], a23.x, w1);
        fma2(acc[3][0], a23.y, w0);  fma2(acc[3][1], a23.y, w1);
        fma2(acc[4][0], a45.x, w0);  fma2(acc[4][1], a45.x, w1);
        fma2(acc[5][0], a45.y, w0);  fma2(acc[5][1], a45.y, w1);
        fma2(acc[6][0], a67.x, w0);  fma2(acc[6][1], a67.x, w1);
        fma2(acc[7][0], a67.y, w0);  fma2(acc[7][1], a67.y, w1);
    }

    if (INPLACE) __syncthreads();          // all reads of `in` complete

    // stage 1: ks0 -> out, ks1 -> red (disjoint, parallel, STS.128)
    if (ks < 2) {
        ull* o = (ks == 0 ? out : red) + c0 * NRP;
#pragma unroll
        for (int cc = 0; cc < 2; ++cc)
#pragma unroll
            for (int rp = 0; rp < NRP; rp += 2)
                *(ulonglong2*)(o + cc * NRP + rp) =
                    make_ulonglong2(acc[rp][cc], acc[rp + 1][cc]);
    }
    __syncthreads();

    // stage 2: ks2 += out, ks3 += red (disjoint, parallel, LDS/STS.128)
    if (ks >= 2) {
        ull* o = (ks == 2 ? out : red) + c0 * NRP;
#pragma unroll
        for (int cc = 0; cc < 2; ++cc)
#pragma unroll
            for (int rp = 0; rp < NRP; rp += 2) {
                ulonglong2 v = *(ulonglong2*)(o + cc * NRP + rp);
                v.x = add2(v.x, acc[rp][cc]);
                v.y = add2(v.y, acc[rp + 1][cc]);
                *(ulonglong2*)(o + cc * NRP + rp) = v;
            }
    }
    __syncthreads();

    // combine + mish spread pass: 2048 ull / 512 threads = 4 each (128-bit ops)
    {
        ulonglong2* ph = (ulonglong2*)(out + tid * 4);
        const ulonglong2* pr = (const ulonglong2*)(red + tid * 4);
#pragma unroll
        for (int j = 0; j < 2; ++j) {
            ulonglong2 h = ph[j], r = pr[j];
            float l0, h0, l1, h1;
            unpack2(add2(h.x, r.x), l0, h0);
            unpack2(add2(h.y, r.y), l1, h1);
            ph[j] = make_ulonglong2(pack2(mishf(l0), mishf(h0)),
                                    pack2(mishf(l1), mishf(h1)));
        }
    }
    __syncthreads();
}

// ---------------------------------------------------------------------------
// Fused sampler: CTA owns 16 rows for all 100 steps. 512 threads.
// ---------------------------------------------------------------------------
__global__ void __launch_bounds__(NTHR, 1) sampler_kernel(
    const float* __restrict__ state,
    const float* __restrict__ x_init,
    const float* __restrict__ noise,
    const float* __restrict__ W1, const float* __restrict__ b1,
    const float* __restrict__ W2, const float* __restrict__ b2,
    const float* __restrict__ W3, const float* __restrict__ b3,
    const float* __restrict__ W4, const float* __restrict__ b4,
    float* __restrict__ out)
{
    __shared__ __align__(16) ull a0[CAT * NRP];        //  7.0 KB  layer-1 input
    __shared__ __align__(16) ull hbuf[HID * NRP];      // 16.0 KB  layers 1-3 (in-place)
    __shared__ __align__(16) ull red[HID * NRP];       // 16.0 KB  partials
    __shared__ __align__(16) ull red4[NRP * ADIM * 4]; //  4.0 KB  L4 partials

    const int tid  = threadIdx.x;
    const int cg   = tid & 127;      // col-pair 0..127
    const int ks   = tid >> 7;       // k-quarter 0..3
    const int row0 = blockIdx.x * RPC;

    // ---- one-time fills (row-pair packed) ----
    if (tid < 128) {                 // x: 16 feats x 8 rp
        int f = tid >> 3, rp = tid & 7;
        a0[f * NRP + rp] = pack2(x_init[(row0 + 2 * rp)     * ADIM + f],
                                 x_init[(row0 + 2 * rp + 1) * ADIM + f]);
    }
    {                                // state: 64 feats x 8 rp = 512
        int f = tid >> 3, rp = tid & 7;
        a0[(ADIM + TDIM + f) * NRP + rp] =
            pack2(state[(row0 + 2 * rp)     * SDIM + f],
                  state[(row0 + 2 * rp + 1) * SDIM + f]);
    }

    for (int s = 0; s < TSTEPS; ++s) {
        const int i = TSTEPS - 1 - s;

        if (tid < 256) {             // temb: 32 feats x 8 rp (row-invariant)
            int f = tid >> 3, rp = tid & 7;
            float t = g_temb[i * TDIM + f];
            a0[(ADIM + f) * NRP + rp] = pack2(t, t);
        }
        __syncthreads();

        dense4ks<CAT, false>(a0,   W1, b1, hbuf, red, cg, ks, tid);
        dense4ks<HID, true >(hbuf, W2, b2, hbuf, red, cg, ks, tid);
        dense4ks<HID, true >(hbuf, W3, b3, hbuf, red, cg, ks, tid);

        // ---- layer 4 (256 -> 16): thread = (k-quarter, rp, c) ----
        {
            const int c  = tid & 15;
            const int rp = (tid >> 4) & 7;
            const int k4 = tid >> 7;        // 0..3
            ull acc = 0;
            const int kb = k4 * 64;
#pragma unroll 8
            for (int kk = 0; kk < 64; ++kk) {
                const int k = kb + kk;
                const float w = W4[k * ADIM + c];
                fma2(acc, hbuf[k * NRP + rp], pack2(w, w));
            }
            red4[(rp * ADIM + c) * 4 + k4] = acc;
        }
        __syncthreads();

        // ---- reduce + posterior (128 threads: rp, c) ----
        if (tid < 128) {
            const int rp = tid >> 4, c = tid & 15;
            const ull* r = red4 + (rp * ADIM + c) * 4;
            ull e = add2(add2(r[0], r[1]), add2(r[2], r[3]));
            float e0, e1; unpack2(e, e0, e1);
            const float bb = b4[c];
            e0 += bb; e1 += bb;

            float x0, x1; unpack2(a0[c * NRP + rp], x0, x1);
            const float sr = g_srac[i], srm = g_sracm1[i];
            const float c1 = g_c1[i],   c2  = g_c2[i];

            float r0 = fminf(fmaxf(sr * x0 - srm * e0, -1.0f), 1.0f);
            float r1 = fminf(fmaxf(sr * x1 - srm * e1, -1.0f), 1.0f);
            float m0 = c1 * r0 + c2 * x0;
            float m1 = c1 * r1 + c2 * x1;

            if (i > 0) {
                const float sg = g_sigma[i];
                const float* nz = noise + (size_t)s * BATCH * ADIM;
                float n0 = nz[(row0 + 2 * rp)     * ADIM + c];
                float n1 = nz[(row0 + 2 * rp + 1) * ADIM + c];
                a0[c * NRP + rp] = pack2(fmaf(sg, n0, m0), fmaf(sg, n1, m1));
            } else {
                out[(row0 + 2 * rp)     * ADIM + c] = fminf(fmaxf(m0, -1.0f), 1.0f);
                out[(row0 + 2 * rp + 1) * ADIM + c] = fminf(fmaxf(m1, -1.0f), 1.0f);
            }
        }
        __syncthreads();
    }
}

// ---------------------------------------------------------------------------
// kernel_launch
// ---------------------------------------------------------------------------
extern "C" void kernel_launch(void* const* d_in, const int* in_sizes, int n_in,
                              void* d_out, int out_size)
{
    const float* state  = (const float*)d_in[0];
    const float* x_init = (const float*)d_in[1];
    const float* noise  = (const float*)d_in[2];
    const float* tW1    = (const float*)d_in[3];
    const float* tb1    = (const float*)d_in[4];
    const float* tW2    = (const float*)d_in[5];
    const float* tb2    = (const float*)d_in[6];
    const float* W1     = (const float*)d_in[7];
    const float* b1     = (const float*)d_in[8];
    const float* W2     = (const float*)d_in[9];
    const float* b2     = (const float*)d_in[10];
    const float* W3     = (const float*)d_in[11];
    const float* b3     = (const float*)d_in[12];
    const float* W4     = (const float*)d_in[13];
    const float* b4     = (const float*)d_in[14];
    float* out          = (float*)d_out;

    prolog_kernel<<<TSTEPS, 256>>>(tW1, tb1, tW2, tb2);
    sampler_kernel<<<NCTA, NTHR>>>(state, x_init, noise,
                                   W1, b1, W2, b2, W3, b3, W4, b4, out);
}

// round 10
// speedup vs baseline: 1.3279x; 1.0036x over previous
#include <cuda_runtime.h>
#include <cuda_bf16.h>
#include <math.h>

// ---------------------------------------------------------------------------
// Problem constants
// ---------------------------------------------------------------------------
#define BATCH     2048
#define SDIM      64
#define ADIM      16
#define HID       256
#define TDIM      32
#define TSTEPS    100
#define CAT       112            // ADIM + TDIM + SDIM
#define RPC       16             // rows per CTA
#define NRP       8              // row-pairs per CTA
#define NCTA      (BATCH / RPC)  // 128
#define NTHR      512            // 128 col-pair threads x 4 k-quarters

typedef unsigned long long ull;

// ---------------------------------------------------------------------------
// Precomputed tables
// ---------------------------------------------------------------------------
__device__ float g_temb[TSTEPS * TDIM];
__device__ float g_srac[TSTEPS];
__device__ float g_sracm1[TSTEPS];
__device__ float g_c1[TSTEPS];
__device__ float g_c2[TSTEPS];
__device__ float g_sigma[TSTEPS];

// ---------------------------------------------------------------------------
// f32x2 helpers
// ---------------------------------------------------------------------------
__device__ __forceinline__ ull pack2(float lo, float hi) {
    ull r; asm("mov.b64 %0, {%1, %2};" : "=l"(r) : "f"(lo), "f"(hi)); return r;
}
__device__ __forceinline__ void unpack2(ull v, float& lo, float& hi) {
    asm("mov.b64 {%0, %1}, %2;" : "=f"(lo), "=f"(hi) : "l"(v));
}
__device__ __forceinline__ void fma2(ull& d, ull a, ull b) {
    asm("fma.rn.f32x2 %0, %1, %2, %0;" : "+l"(d) : "l"(a), "l"(b));
}
__device__ __forceinline__ ull add2(ull a, ull b) {
    ull r; asm("add.rn.f32x2 %0, %1, %2;" : "=l"(r) : "l"(a), "l"(b)); return r;
}

// ---------------------------------------------------------------------------
// Fast exact-algebra mish:
//   mish(x) = x * tanh(softplus(x));  e^{softplus(x)} = 1 + e^x  (exact)
//   => tanh(sp) = ((1+u)^2 - 1)/((1+u)^2 + 1) = v/(v+2),  v = u^2 + 2u, u = e^x
// ex2.approx / rcp.approx errors ~2^-22 -> mish accurate to ~1e-6.
// Clamp x<=40 so u^2 stays finite (x>=40 => ratio==1 to fp32 precision).
// ---------------------------------------------------------------------------
__device__ __forceinline__ float mishf(float x) {
    const float LOG2E = 1.4426950408889634f;
    float xc = fminf(x, 40.0f);
    float u;
    asm("ex2.approx.f32 %0, %1;" : "=f"(u) : "f"(xc * LOG2E));
    float v = fmaf(u, u, u + u);          // u^2 + 2u
    float r;
    asm("rcp.approx.f32 %0, %1;" : "=f"(r) : "f"(v + 2.0f));
    return x * v * r;
}

// ---------------------------------------------------------------------------
// Prolog: VP schedule in f64 + per-timestep time-MLP (batch-invariant).
// ---------------------------------------------------------------------------
__global__ void __launch_bounds__(256) prolog_kernel(
    const float* __restrict__ tW1, const float* __restrict__ tb1,
    const float* __restrict__ tW2, const float* __restrict__ tb2)
{
    const int tid = threadIdx.x;
    const int i   = blockIdx.x;

    if (i == 0 && tid == 0) {
        const double T = (double)TSTEPS, bmax = 10.0, bmin = 0.1;
        double ac = 1.0;
        for (int idx = 0; idx < TSTEPS; ++idx) {
            double t      = (double)(idx + 1);
            double alpha  = exp(-bmin / T - 0.5 * (bmax - bmin) * (2.0 * t - 1.0) / (T * T));
            double beta   = 1.0 - alpha;
            double acp    = ac;
            ac            = ac * alpha;
            g_srac[idx]   = (float)sqrt(1.0 / ac);
            g_sracm1[idx] = (float)sqrt(1.0 / ac - 1.0);
            g_c1[idx]     = (float)(beta * sqrt(acp) / (1.0 - ac));
            g_c2[idx]     = (float)((1.0 - acp) * sqrt(alpha) / (1.0 - ac));
            double pv     = beta * (1.0 - acp) / (1.0 - ac);
            if (pv < 1e-20) pv = 1e-20;
            g_sigma[idx]  = (float)exp(0.5 * log(pv));
        }
    }

    __shared__ float emb[TDIM];
    __shared__ float hid[HID];

    if (tid < TDIM) {
        int   j    = tid & 15;
        float freq = expf((float)j * (-logf(10000.0f) / 15.0f));
        float ang  = (float)i * freq;
        emb[tid]   = (tid < 16) ? sinf(ang) : cosf(ang);
    }
    __syncthreads();
    {
        float a = tb1[tid];
#pragma unroll
        for (int j = 0; j < TDIM; ++j)
            a = fmaf(emb[j], tW1[j * HID + tid], a);
        hid[tid] = mishf(a);
    }
    __syncthreads();
    if (tid < TDIM) {
        float a = tb2[tid];
#pragma unroll 8
        for (int h = 0; h < HID; ++h)
            a = fmaf(hid[h], tW2[h * TDIM + tid], a);
        g_temb[i * TDIM + tid] = a;
    }
}

// ---------------------------------------------------------------------------
// Dense layer 256-out, thread tile = 8 row-pairs x 2 cols, k-split 4.
//   in  : smem ull[K][NRP] row-pair packed activations (broadcast LDS.128)
//   W   : gmem fp32 [K][256]; 2 cols via LDG.64 (coalesced 256B/warp)
//   out : smem ull[256][NRP] — MAY alias `in`
//   red : smem ull[256][NRP]
// Staged parallel reduction (all stores/loads vectorized to 128-bit):
// {ks0->out(+bias), ks1->red} then {ks2+=out, ks3+=red}, then a mish spread
// pass combines out+red. 16 warps/SM hide LDS/LDG latency.
// ---------------------------------------------------------------------------
template <int K, bool INPLACE>
__device__ __forceinline__ void dense4ks(
    const ull* __restrict__ in,
    const float* __restrict__ W,
    const float* __restrict__ b,
    ull* __restrict__ out,
    ull* __restrict__ red,
    int cg, int ks, int tid)
{
    const int c0 = cg * 2;
    ull acc[NRP][2];
    if (ks == 0) {
        const ull b0 = pack2(b[c0], b[c0]);
        const ull b1 = pack2(b[c0 + 1], b[c0 + 1]);
#pragma unroll
        for (int rp = 0; rp < NRP; ++rp) { acc[rp][0] = b0; acc[rp][1] = b1; }
    } else {
#pragma unroll
        for (int rp = 0; rp < NRP; ++rp) { acc[rp][0] = 0; acc[rp][1] = 0; }
    }

    const int kn = K / 4;
    const int kb = ks * kn;
    const ull*   ip = in + kb * NRP;
    const float* wp = W + kb * HID + c0;

#pragma unroll 8
    for (int kk = 0; kk < kn; ++kk) {
        const ulonglong2 a01 = *(const ulonglong2*)(ip + 0);
        const ulonglong2 a23 = *(const ulonglong2*)(ip + 2);
        const ulonglong2 a45 = *(const ulonglong2*)(ip + 4);
        const ulonglong2 a67 = *(const ulonglong2*)(ip + 6);
        const float2 wf = *(const float2*)wp;
        ip += NRP;
        wp += HID;
        const ull w0 = pack2(wf.x, wf.x);
        const ull w1 = pack2(wf.y, wf.y);
        fma2(acc[0][0], a01.x, w0);  fma2(acc[0][1], a01.x, w1);
        fma2(acc[1][0], a01.y, w0);  fma2(acc[1][1], a01.y, w1);
        fma2(acc[2][0], a23.x, w0);  fma2(acc[2][1], a23.x, w1);
        fma2(acc[3][0], a23.y, w0);  fma2(acc[3][1], a23.y, w1);
        fma2(acc[4][0], a45.x, w0);  fma2(acc[4][1], a45.x, w1);
        fma2(acc[5][0], a45.y, w0);  fma2(acc[5][1], a45.y, w1);
        fma2(acc[6][0], a67.x, w0);  fma2(acc[6][1], a67.x, w1);
        fma2(acc[7][0], a67.y, w0);  fma2(acc[7][1], a67.y, w1);
    }

    if (INPLACE) __syncthreads();          // all reads of `in` complete

    // stage 1: ks0 -> out, ks1 -> red (disjoint, parallel, STS.128)
    if (ks < 2) {
        ull* o = (ks == 0 ? out : red) + c0 * NRP;
#pragma unroll
        for (int cc = 0; cc < 2; ++cc)
#pragma unroll
            for (int rp = 0; rp < NRP; rp += 2)
                *(ulonglong2*)(o + cc * NRP + rp) =
                    make_ulonglong2(acc[rp][cc], acc[rp + 1][cc]);
    }
    __syncthreads();

    // stage 2: ks2 += out, ks3 += red (disjoint, parallel, LDS/STS.128)
    if (ks >= 2) {
        ull* o = (ks == 2 ? out : red) + c0 * NRP;
#pragma unroll
        for (int cc = 0; cc < 2; ++cc)
#pragma unroll
            for (int rp = 0; rp < NRP; rp += 2) {
                ulonglong2 v = *(ulonglong2*)(o + cc * NRP + rp);
                v.x = add2(v.x, acc[rp][cc]);
                v.y = add2(v.y, acc[rp + 1][cc]);
                *(ulonglong2*)(o + cc * NRP + rp) = v;
            }
    }
    __syncthreads();

    // combine + mish spread pass: 2048 ull / 512 threads = 4 each (128-bit ops)
    {
        ulonglong2* ph = (ulonglong2*)(out + tid * 4);
        const ulonglong2* pr = (const ulonglong2*)(red + tid * 4);
#pragma unroll
        for (int j = 0; j < 2; ++j) {
            ulonglong2 h = ph[j], r = pr[j];
            float l0, h0, l1, h1;
            unpack2(add2(h.x, r.x), l0, h0);
            unpack2(add2(h.y, r.y), l1, h1);
            ph[j] = make_ulonglong2(pack2(mishf(l0), mishf(h0)),
                                    pack2(mishf(l1), mishf(h1)));
        }
    }
    __syncthreads();
}

// ---------------------------------------------------------------------------
// Fused sampler: CTA owns 16 rows for all 100 steps. 512 threads.
// ---------------------------------------------------------------------------
__global__ void __launch_bounds__(NTHR, 1) sampler_kernel(
    const float* __restrict__ state,
    const float* __restrict__ x_init,
    const float* __restrict__ noise,
    const float* __restrict__ W1, const float* __restrict__ b1,
    const float* __restrict__ W2, const float* __restrict__ b2,
    const float* __restrict__ W3, const float* __restrict__ b3,
    const float* __restrict__ W4, const float* __restrict__ b4,
    float* __restrict__ out)
{
    __shared__ __align__(16) ull a0[CAT * NRP];        //  7.0 KB  layer-1 input
    __shared__ __align__(16) ull hbuf[HID * NRP];      // 16.0 KB  layers 1-3 (in-place)
    __shared__ __align__(16) ull red[HID * NRP];       // 16.0 KB  partials
    __shared__ __align__(16) ull red4[NRP * ADIM * 4]; //  4.0 KB  L4 partials

    const int tid  = threadIdx.x;
    const int cg   = tid & 127;      // col-pair 0..127
    const int ks   = tid >> 7;       // k-quarter 0..3
    const int row0 = blockIdx.x * RPC;

    // ---- one-time fills (row-pair packed) ----
    if (tid < 128) {                 // x: 16 feats x 8 rp
        int f = tid >> 3, rp = tid & 7;
        a0[f * NRP + rp] = pack2(x_init[(row0 + 2 * rp)     * ADIM + f],
                                 x_init[(row0 + 2 * rp + 1) * ADIM + f]);
    }
    {                                // state: 64 feats x 8 rp = 512
        int f = tid >> 3, rp = tid & 7;
        a0[(ADIM + TDIM + f) * NRP + rp] =
            pack2(state[(row0 + 2 * rp)     * SDIM + f],
                  state[(row0 + 2 * rp + 1) * SDIM + f]);
    }

    for (int s = 0; s < TSTEPS; ++s) {
        const int i = TSTEPS - 1 - s;

        if (tid < 256) {             // temb: 32 feats x 8 rp (row-invariant)
            int f = tid >> 3, rp = tid & 7;
            float t = g_temb[i * TDIM + f];
            a0[(ADIM + f) * NRP + rp] = pack2(t, t);
        }
        __syncthreads();

        dense4ks<CAT, false>(a0,   W1, b1, hbuf, red, cg, ks, tid);
        dense4ks<HID, true >(hbuf, W2, b2, hbuf, red, cg, ks, tid);
        dense4ks<HID, true >(hbuf, W3, b3, hbuf, red, cg, ks, tid);

        // ---- layer 4 (256 -> 16): thread = (k-quarter, rp, c) ----
        {
            const int c  = tid & 15;
            const int rp = (tid >> 4) & 7;
            const int k4 = tid >> 7;        // 0..3
            ull acc = 0;
            const int kb = k4 * 64;
#pragma unroll 8
            for (int kk = 0; kk < 64; ++kk) {
                const int k = kb + kk;
                const float w = W4[k * ADIM + c];
                fma2(acc, hbuf[k * NRP + rp], pack2(w, w));
            }
            red4[(rp * ADIM + c) * 4 + k4] = acc;
        }
        __syncthreads();

        // ---- reduce + posterior (128 threads: rp, c) ----
        if (tid < 128) {
            const int rp = tid >> 4, c = tid & 15;
            const ull* r = red4 + (rp * ADIM + c) * 4;
            ull e = add2(add2(r[0], r[1]), add2(r[2], r[3]));
            float e0, e1; unpack2(e, e0, e1);
            const float bb = b4[c];
            e0 += bb; e1 += bb;

            float x0, x1; unpack2(a0[c * NRP + rp], x0, x1);
            const float sr = g_srac[i], srm = g_sracm1[i];
            const float c1 = g_c1[i],   c2  = g_c2[i];

            float r0 = fminf(fmaxf(sr * x0 - srm * e0, -1.0f), 1.0f);
            float r1 = fminf(fmaxf(sr * x1 - srm * e1, -1.0f), 1.0f);
            float m0 = c1 * r0 + c2 * x0;
            float m1 = c1 * r1 + c2 * x1;

            if (i > 0) {
                const float sg = g_sigma[i];
                const float* nz = noise + (size_t)s * BATCH * ADIM;
                float n0 = nz[(row0 + 2 * rp)     * ADIM + c];
                float n1 = nz[(row0 + 2 * rp + 1) * ADIM + c];
                a0[c * NRP + rp] = pack2(fmaf(sg, n0, m0), fmaf(sg, n1, m1));
            } else {
                out[(row0 + 2 * rp)     * ADIM + c] = fminf(fmaxf(m0, -1.0f), 1.0f);
                out[(row0 + 2 * rp + 1) * ADIM + c] = fminf(fmaxf(m1, -1.0f), 1.0f);
            }
        }
        __syncthreads();
    }
}

// ---------------------------------------------------------------------------
// kernel_launch
// ---------------------------------------------------------------------------
extern "C" void kernel_launch(void* const* d_in, const int* in_sizes, int n_in,
                              void* d_out, int out_size)
{
    const float* state  = (const float*)d_in[0];
    const float* x_init = (const float*)d_in[1];
    const float* noise  = (const float*)d_in[2];
    const float* tW1    = (const float*)d_in[3];
    const float* tb1    = (const float*)d_in[4];
    const float* tW2    = (const float*)d_in[5];
    const float* tb2    = (const float*)d_in[6];
    const float* W1     = (const float*)d_in[7];
    const float* b1     = (const float*)d_in[8];
    const float* W2     = (const float*)d_in[9];
    const float* b2     = (const float*)d_in[10];
    const float* W3     = (const float*)d_in[11];
    const float* b3     = (const float*)d_in[12];
    const float* W4     = (const float*)d_in[13];
    const float* b4     = (const float*)d_in[14];
    float* out          = (float*)d_out;

    prolog_kernel<<<TSTEPS, 256>>>(tW1, tb1, tW2, tb2);
    sampler_kernel<<<NCTA, NTHR>>>(state, x_init, noise,
                                   W1, b1, W2, b2, W3, b3, W4, b4, out);
}

// round 11
// speedup vs baseline: 1.8528x; 1.3953x over previous
#include <cuda_runtime.h>
#include <cuda_bf16.h>
#include <math.h>

// ---------------------------------------------------------------------------
// Problem constants
// ---------------------------------------------------------------------------
#define BATCH     2048
#define SDIM      64
#define ADIM      16
#define HID       256
#define TDIM      32
#define TSTEPS    100
#define CAT       112            // ADIM + TDIM + SDIM
#define RPC       16             // rows per CTA
#define NRP       8              // row-pairs per CTA
#define NCTA      (BATCH / RPC)  // 128
#define NTHR      512            // 128 col-pair threads x 4 k-quarters
#define GSTR      18             // ull per 2-col group (16 data + 2 pad)

typedef unsigned long long ull;

// padded layout: value (col c, row-pair rp) lives at (c>>1)*GSTR + (c&1)*8 + rp
__device__ __forceinline__ int lay(int c, int rp) {
    return (c >> 1) * GSTR + (c & 1) * 8 + rp;
}

// ---------------------------------------------------------------------------
// Precomputed tables
// ---------------------------------------------------------------------------
__device__ float g_temb[TSTEPS * TDIM];
__device__ float g_srac[TSTEPS];
__device__ float g_sracm1[TSTEPS];
__device__ float g_c1[TSTEPS];
__device__ float g_c2[TSTEPS];
__device__ float g_sigma[TSTEPS];

// ---------------------------------------------------------------------------
// f32x2 helpers
// ---------------------------------------------------------------------------
__device__ __forceinline__ ull pack2(float lo, float hi) {
    ull r; asm("mov.b64 %0, {%1, %2};" : "=l"(r) : "f"(lo), "f"(hi)); return r;
}
__device__ __forceinline__ void unpack2(ull v, float& lo, float& hi) {
    asm("mov.b64 {%0, %1}, %2;" : "=f"(lo), "=f"(hi) : "l"(v));
}
__device__ __forceinline__ void fma2(ull& d, ull a, ull b) {
    asm("fma.rn.f32x2 %0, %1, %2, %0;" : "+l"(d) : "l"(a), "l"(b));
}
__device__ __forceinline__ ull add2(ull a, ull b) {
    ull r; asm("add.rn.f32x2 %0, %1, %2;" : "=l"(r) : "l"(a), "l"(b)); return r;
}

// ---------------------------------------------------------------------------
// Fast exact-algebra mish:
//   mish(x) = x * tanh(softplus(x));  e^{softplus(x)} = 1 + e^x  (exact)
//   tanh(sp) = v/(v+2),  v = u^2 + 2u,  u = e^x.  (~1e-6 accurate)
// ---------------------------------------------------------------------------
__device__ __forceinline__ float mishf(float x) {
    const float LOG2E = 1.4426950408889634f;
    float xc = fminf(x, 40.0f);
    float u;
    asm("ex2.approx.f32 %0, %1;" : "=f"(u) : "f"(xc * LOG2E));
    float v = fmaf(u, u, u + u);          // u^2 + 2u
    float r;
    asm("rcp.approx.f32 %0, %1;" : "=f"(r) : "f"(v + 2.0f));
    return x * v * r;
}

// ---------------------------------------------------------------------------
// Prolog: VP schedule in f64 + per-timestep time-MLP (batch-invariant).
// ---------------------------------------------------------------------------
__global__ void __launch_bounds__(256) prolog_kernel(
    const float* __restrict__ tW1, const float* __restrict__ tb1,
    const float* __restrict__ tW2, const float* __restrict__ tb2)
{
    const int tid = threadIdx.x;
    const int i   = blockIdx.x;

    if (i == 0 && tid == 0) {
        const double T = (double)TSTEPS, bmax = 10.0, bmin = 0.1;
        double ac = 1.0;
        for (int idx = 0; idx < TSTEPS; ++idx) {
            double t      = (double)(idx + 1);
            double alpha  = exp(-bmin / T - 0.5 * (bmax - bmin) * (2.0 * t - 1.0) / (T * T));
            double beta   = 1.0 - alpha;
            double acp    = ac;
            ac            = ac * alpha;
            g_srac[idx]   = (float)sqrt(1.0 / ac);
            g_sracm1[idx] = (float)sqrt(1.0 / ac - 1.0);
            g_c1[idx]     = (float)(beta * sqrt(acp) / (1.0 - ac));
            g_c2[idx]     = (float)((1.0 - acp) * sqrt(alpha) / (1.0 - ac));
            double pv     = beta * (1.0 - acp) / (1.0 - ac);
            if (pv < 1e-20) pv = 1e-20;
            g_sigma[idx]  = (float)exp(0.5 * log(pv));
        }
    }

    __shared__ float emb[TDIM];
    __shared__ float hid[HID];

    if (tid < TDIM) {
        int   j    = tid & 15;
        float freq = expf((float)j * (-logf(10000.0f) / 15.0f));
        float ang  = (float)i * freq;
        emb[tid]   = (tid < 16) ? sinf(ang) : cosf(ang);
    }
    __syncthreads();
    {
        // full-precision mish here (one-time cost, keeps temb exact-ish)
        float a = tb1[tid];
#pragma unroll
        for (int j = 0; j < TDIM; ++j)
            a = fmaf(emb[j], tW1[j * HID + tid], a);
        float sp = fmaxf(a, 0.0f) + log1pf(expf(-fabsf(a)));
        hid[tid] = a * tanhf(sp);
    }
    __syncthreads();
    if (tid < TDIM) {
        float a = tb2[tid];
#pragma unroll 8
        for (int h = 0; h < HID; ++h)
            a = fmaf(hid[h], tW2[h * TDIM + tid], a);
        g_temb[i * TDIM + tid] = a;
    }
}

// ---------------------------------------------------------------------------
// Dense layer 256-out, thread tile = 8 row-pairs x 2 cols, k-split 4.
// Activations live in the GSTR-padded layout -> mainloop LDS.128 broadcasts
// stay at 4 wf/k AND reduction-stage STS/LDS.128 run at the 4-wf floor
// (the unpadded layout had 32-way bank conflicts: 128B lane stride).
// Staged parallel reduction: {ks0->out(+bias), ks1->red}, {ks2+=out,
// ks3+=red}, then a combine+mish spread pass.
// ---------------------------------------------------------------------------
template <int K, bool INPLACE>
__device__ __forceinline__ void dense4ks(
    const ull* __restrict__ in,
    const float* __restrict__ W,
    const float* __restrict__ b,
    ull* __restrict__ out,
    ull* __restrict__ red,
    int cg, int ks, int tid)
{
    const int c0 = cg * 2;
    ull acc[NRP][2];
    if (ks == 0) {
        const ull b0 = pack2(b[c0], b[c0]);
        const ull b1 = pack2(b[c0 + 1], b[c0 + 1]);
#pragma unroll
        for (int rp = 0; rp < NRP; ++rp) { acc[rp][0] = b0; acc[rp][1] = b1; }
    } else {
#pragma unroll
        for (int rp = 0; rp < NRP; ++rp) { acc[rp][0] = 0; acc[rp][1] = 0; }
    }

    const int kn = K / 4;              // even for K=112 or 256
    const int kb = ks * kn;            // even
    const ull*   ip = in + (kb >> 1) * GSTR;
    const float* wp = W + kb * HID + c0;

#pragma unroll 4
    for (int kk = 0; kk < kn; kk += 2) {
        // k even half of the group
        {
            const ulonglong2 a01 = *(const ulonglong2*)(ip + 0);
            const ulonglong2 a23 = *(const ulonglong2*)(ip + 2);
            const ulonglong2 a45 = *(const ulonglong2*)(ip + 4);
            const ulonglong2 a67 = *(const ulonglong2*)(ip + 6);
            const float2 wf = *(const float2*)wp;
            const ull w0 = pack2(wf.x, wf.x);
            const ull w1 = pack2(wf.y, wf.y);
            fma2(acc[0][0], a01.x, w0);  fma2(acc[0][1], a01.x, w1);
            fma2(acc[1][0], a01.y, w0);  fma2(acc[1][1], a01.y, w1);
            fma2(acc[2][0], a23.x, w0);  fma2(acc[2][1], a23.x, w1);
            fma2(acc[3][0], a23.y, w0);  fma2(acc[3][1], a23.y, w1);
            fma2(acc[4][0], a45.x, w0);  fma2(acc[4][1], a45.x, w1);
            fma2(acc[5][0], a45.y, w0);  fma2(acc[5][1], a45.y, w1);
            fma2(acc[6][0], a67.x, w0);  fma2(acc[6][1], a67.x, w1);
            fma2(acc[7][0], a67.y, w0);  fma2(acc[7][1], a67.y, w1);
        }
        // k odd half of the group
        {
            const ulonglong2 a01 = *(const ulonglong2*)(ip + 8);
            const ulonglong2 a23 = *(const ulonglong2*)(ip + 10);
            const ulonglong2 a45 = *(const ulonglong2*)(ip + 12);
            const ulonglong2 a67 = *(const ulonglong2*)(ip + 14);
            const float2 wf = *(const float2*)(wp + HID);
            const ull w0 = pack2(wf.x, wf.x);
            const ull w1 = pack2(wf.y, wf.y);
            fma2(acc[0][0], a01.x, w0);  fma2(acc[0][1], a01.x, w1);
            fma2(acc[1][0], a01.y, w0);  fma2(acc[1][1], a01.y, w1);
            fma2(acc[2][0], a23.x, w0);  fma2(acc[2][1], a23.x, w1);
            fma2(acc[3][0], a23.y, w0);  fma2(acc[3][1], a23.y, w1);
            fma2(acc[4][0], a45.x, w0);  fma2(acc[4][1], a45.x, w1);
            fma2(acc[5][0], a45.y, w0);  fma2(acc[5][1], a45.y, w1);
            fma2(acc[6][0], a67.x, w0);  fma2(acc[6][1], a67.x, w1);
            fma2(acc[7][0], a67.y, w0);  fma2(acc[7][1], a67.y, w1);
        }
        ip += GSTR;
        wp += 2 * HID;
    }

    if (INPLACE) __syncthreads();          // all reads of `in` complete

    // stage 1: ks0 -> out, ks1 -> red (disjoint, parallel; 4-wf-floor STS.128)
    if (ks < 2) {
        ull* o = (ks == 0 ? out : red) + cg * GSTR;
#pragma unroll
        for (int cc = 0; cc < 2; ++cc)
#pragma unroll
            for (int rp = 0; rp < NRP; rp += 2)
                *(ulonglong2*)(o + cc * 8 + rp) =
                    make_ulonglong2(acc[rp][cc], acc[rp + 1][cc]);
    }
    __syncthreads();

    // stage 2: ks2 += out, ks3 += red (disjoint, parallel)
    if (ks >= 2) {
        ull* o = (ks == 2 ? out : red) + cg * GSTR;
#pragma unroll
        for (int cc = 0; cc < 2; ++cc)
#pragma unroll
            for (int rp = 0; rp < NRP; rp += 2) {
                ulonglong2 v = *(ulonglong2*)(o + cc * 8 + rp);
                v.x = add2(v.x, acc[rp][cc]);
                v.y = add2(v.y, acc[rp + 1][cc]);
                *(ulonglong2*)(o + cc * 8 + rp) = v;
            }
    }
    __syncthreads();

    // combine + mish spread pass: data ull d = tid*4..+3, padded address
    {
        const int d0   = tid * 4;
        const int base = (d0 >> 4) * GSTR + (d0 & 15);
        ulonglong2* ph = (ulonglong2*)(out + base);
        const ulonglong2* pr = (const ulonglong2*)(red + base);
#pragma unroll
        for (int j = 0; j < 2; ++j) {
            ulonglong2 h = ph[j], r = pr[j];
            float l0, h0, l1, h1;
            unpack2(add2(h.x, r.x), l0, h0);
            unpack2(add2(h.y, r.y), l1, h1);
            ph[j] = make_ulonglong2(pack2(mishf(l0), mishf(h0)),
                                    pack2(mishf(l1), mishf(h1)));
        }
    }
    __syncthreads();
}

// ---------------------------------------------------------------------------
// Fused sampler: CTA owns 16 rows for all 100 steps. 512 threads.
// ---------------------------------------------------------------------------
__global__ void __launch_bounds__(NTHR, 1) sampler_kernel(
    const float* __restrict__ state,
    const float* __restrict__ x_init,
    const float* __restrict__ noise,
    const float* __restrict__ W1, const float* __restrict__ b1,
    const float* __restrict__ W2, const float* __restrict__ b2,
    const float* __restrict__ W3, const float* __restrict__ b3,
    const float* __restrict__ W4, const float* __restrict__ b4,
    float* __restrict__ out)
{
    __shared__ __align__(16) ull a0[(CAT / 2) * GSTR];   //  7.9 KB layer-1 input
    __shared__ __align__(16) ull hbuf[(HID / 2) * GSTR]; // 18.0 KB layers 1-3
    __shared__ __align__(16) ull red[(HID / 2) * GSTR];  // 18.0 KB partials
    // L4 partials (512 ull) alias `red` — dead after the L3 combine pass.
    ull* red4 = red;

    const int tid  = threadIdx.x;
    const int cg   = tid & 127;      // col-pair 0..127
    const int ks   = tid >> 7;       // k-quarter 0..3
    const int row0 = blockIdx.x * RPC;

    // ---- one-time fills (padded, row-pair packed) ----
    if (tid < 128) {                 // x: 16 feats x 8 rp
        int f = tid >> 3, rp = tid & 7;
        a0[lay(f, rp)] = pack2(x_init[(row0 + 2 * rp)     * ADIM + f],
                               x_init[(row0 + 2 * rp + 1) * ADIM + f]);
    }
    {                                // state: 64 feats x 8 rp = 512
        int f = tid >> 3, rp = tid & 7;
        a0[lay(ADIM + TDIM + f, rp)] =
            pack2(state[(row0 + 2 * rp)     * SDIM + f],
                  state[(row0 + 2 * rp + 1) * SDIM + f]);
    }

    for (int s = 0; s < TSTEPS; ++s) {
        const int i = TSTEPS - 1 - s;

        if (tid < 256) {             // temb: 32 feats x 8 rp (row-invariant)
            int f = tid >> 3, rp = tid & 7;
            float t = g_temb[i * TDIM + f];
            a0[lay(ADIM + f, rp)] = pack2(t, t);
        }
        __syncthreads();

        dense4ks<CAT, false>(a0,   W1, b1, hbuf, red, cg, ks, tid);
        dense4ks<HID, true >(hbuf, W2, b2, hbuf, red, cg, ks, tid);
        dense4ks<HID, true >(hbuf, W3, b3, hbuf, red, cg, ks, tid);

        // ---- layer 4 (256 -> 16): thread = (k-quarter, rp, c) ----
        {
            const int c  = tid & 15;
            const int rp = (tid >> 4) & 7;
            const int k4 = tid >> 7;        // 0..3
            ull acc = 0;
            const int kb = k4 * 64;
#pragma unroll 8
            for (int kk = 0; kk < 64; ++kk) {
                const int k = kb + kk;
                const float w = W4[k * ADIM + c];
                fma2(acc, hbuf[lay(k, rp)], pack2(w, w));
            }
            red4[(rp * ADIM + c) * 4 + k4] = acc;
        }
        __syncthreads();

        // ---- reduce + posterior (128 threads: rp, c) ----
        if (tid < 128) {
            const int rp = tid >> 4, c = tid & 15;
            const ull* r = red4 + (rp * ADIM + c) * 4;
            ull e = add2(add2(r[0], r[1]), add2(r[2], r[3]));
            float e0, e1; unpack2(e, e0, e1);
            const float bb = b4[c];
            e0 += bb; e1 += bb;

            float x0, x1; unpack2(a0[lay(c, rp)], x0, x1);
            const float sr = g_srac[i], srm = g_sracm1[i];
            const float c1 = g_c1[i],   c2  = g_c2[i];

            float r0 = fminf(fmaxf(sr * x0 - srm * e0, -1.0f), 1.0f);
            float r1 = fminf(fmaxf(sr * x1 - srm * e1, -1.0f), 1.0f);
            float m0 = c1 * r0 + c2 * x0;
            float m1 = c1 * r1 + c2 * x1;

            if (i > 0) {
                const float sg = g_sigma[i];
                const float* nz = noise + (size_t)s * BATCH * ADIM;
                float n0 = nz[(row0 + 2 * rp)     * ADIM + c];
                float n1 = nz[(row0 + 2 * rp + 1) * ADIM + c];
                a0[lay(c, rp)] = pack2(fmaf(sg, n0, m0), fmaf(sg, n1, m1));
            } else {
                out[(row0 + 2 * rp)     * ADIM + c] = fminf(fmaxf(m0, -1.0f), 1.0f);
                out[(row0 + 2 * rp + 1) * ADIM + c] = fminf(fmaxf(m1, -1.0f), 1.0f);
            }
        }
        __syncthreads();
    }
}

// ---------------------------------------------------------------------------
// kernel_launch
// ---------------------------------------------------------------------------
extern "C" void kernel_launch(void* const* d_in, const int* in_sizes, int n_in,
                              void* d_out, int out_size)
{
    const float* state  = (const float*)d_in[0];
    const float* x_init = (const float*)d_in[1];
    const float* noise  = (const float*)d_in[2];
    const float* tW1    = (const float*)d_in[3];
    const float* tb1    = (const float*)d_in[4];
    const float* tW2    = (const float*)d_in[5];
    const float* tb2    = (const float*)d_in[6];
    const float* W1     = (const float*)d_in[7];
    const float* b1     = (const float*)d_in[8];
    const float* W2     = (const float*)d_in[9];
    const float* b2     = (const float*)d_in[10];
    const float* W3     = (const float*)d_in[11];
    const float* b3     = (const float*)d_in[12];
    const float* W4     = (const float*)d_in[13];
    const float* b4     = (const float*)d_in[14];
    float* out          = (float*)d_out;

    prolog_kernel<<<TSTEPS, 256>>>(tW1, tb1, tW2, tb2);
    sampler_kernel<<<NCTA, NTHR>>>(state, x_init, noise,
                                   W1, b1, W2, b2, W3, b3, W4, b4, out);
}